// round 3
// baseline (speedup 1.0000x reference)
#include <cuda_runtime.h>
#include <cuda_bf16.h>
#include <math.h>

#define Bc   4
#define Pc   1024
#define Dc   512
#define Hc   8
#define DKc  64
#define HALFW 32
#define CONCAT_P (2*Pc)

__device__ float g_Q[Bc * Pc * Dc];
__device__ float g_K[Bc * Pc * Dc];
__device__ float g_V[Bc * Pc * Dc];
__device__ float g_concat[Bc * CONCAT_P * Dc];

struct GemmArgs { const float* A; const float* W; const float* bias; float* C; };

// ---------------------------------------------------------------------------
// TF32 3-term-split GEMM: C[M,N] = A[M,K] @ W[K,N] + bias[N], fp32-accurate.
// Block 128x128, BK=16, 256 threads (8 warps, 2(m) x 4(n)), warp tile 64x32,
// mma.sync.m16n8k8.tf32. Each fp32 operand split a = hi + lo (hi = rna-tf32);
// accumulate hi*hi + hi*lo + lo*hi  (lo*lo ~ 2^-22, dropped).
// ---------------------------------------------------------------------------
__device__ __forceinline__ void mma_tf32(float* d, const unsigned* a, const unsigned* b)
{
    asm volatile(
        "mma.sync.aligned.m16n8k8.row.col.f32.tf32.tf32.f32 "
        "{%0,%1,%2,%3}, {%4,%5,%6,%7}, {%8,%9}, {%0,%1,%2,%3};"
        : "+f"(d[0]), "+f"(d[1]), "+f"(d[2]), "+f"(d[3])
        : "r"(a[0]), "r"(a[1]), "r"(a[2]), "r"(a[3]), "r"(b[0]), "r"(b[1]));
}

__device__ __forceinline__ unsigned cvt_tf32(float x)
{
    unsigned h;
    asm("cvt.rna.tf32.f32 %0, %1;" : "=r"(h) : "f"(x));
    return h;
}

__device__ __forceinline__
void gemm_tf32_body(const float* __restrict__ A, const float* __restrict__ W,
                    const float* __restrict__ bias, float* __restrict__ C,
                    int M, int N, int K)
{
    __shared__ float As[128 * 20];   // [m][k], stride 20 (conflict-free frag reads)
    __shared__ float Ws[16 * 136];   // [k][n], stride 136

    int tid  = threadIdx.x;
    int lane = tid & 31;
    int warp = tid >> 5;
    int wm = (warp & 1) * 64;       // warp m offset in block
    int wn = (warp >> 1) * 32;      // warp n offset in block
    int row0 = blockIdx.y * 128;
    int col0 = blockIdx.x * 128;

    // global->smem load indices
    int a_r = tid >> 1;             // 0..127
    int a_k = (tid & 1) * 8;        // 0 or 8
    int w_k = tid >> 5;             // 0..7 (and +8)
    int w_n = (tid & 31) * 4;       // 0..124

    float d[4][4][4];
#pragma unroll
    for (int i = 0; i < 4; i++)
#pragma unroll
        for (int j = 0; j < 4; j++)
#pragma unroll
            for (int r = 0; r < 4; r++) d[i][j][r] = 0.f;

    for (int k0 = 0; k0 < K; k0 += 16) {
        float4 x0 = *(const float4*)&A[(long long)(row0 + a_r) * K + k0 + a_k];
        float4 x1 = *(const float4*)&A[(long long)(row0 + a_r) * K + k0 + a_k + 4];
        *(float4*)&As[a_r * 20 + a_k]     = x0;
        *(float4*)&As[a_r * 20 + a_k + 4] = x1;
        float4 w0 = *(const float4*)&W[(long long)(k0 + w_k) * N + col0 + w_n];
        float4 w1 = *(const float4*)&W[(long long)(k0 + w_k + 8) * N + col0 + w_n];
        *(float4*)&Ws[w_k * 136 + w_n]       = w0;
        *(float4*)&Ws[(w_k + 8) * 136 + w_n] = w1;
        __syncthreads();

#pragma unroll
        for (int kk = 0; kk < 16; kk += 8) {
            unsigned ahi[4][4], alo[4][4];
#pragma unroll
            for (int im = 0; im < 4; im++) {
                int rbase = wm + im * 16 + (lane >> 2);
                int cbase = kk + (lane & 3);
#pragma unroll
                for (int r = 0; r < 4; r++) {
                    int row = rbase + (r & 1) * 8;
                    int col = cbase + (r >> 1) * 4;
                    float v = As[row * 20 + col];
                    unsigned h = cvt_tf32(v);
                    ahi[im][r] = h;
                    alo[im][r] = __float_as_uint(v - __uint_as_float(h));
                }
            }
            unsigned bhi[4][2], blo[4][2];
#pragma unroll
            for (int in_ = 0; in_ < 4; in_++) {
                int cb = wn + in_ * 8 + (lane >> 2);
#pragma unroll
                for (int r = 0; r < 2; r++) {
                    int rowb = kk + (lane & 3) + r * 4;
                    float v = Ws[rowb * 136 + cb];
                    unsigned h = cvt_tf32(v);
                    bhi[in_][r] = h;
                    blo[in_][r] = __float_as_uint(v - __uint_as_float(h));
                }
            }
#pragma unroll
            for (int im = 0; im < 4; im++)
#pragma unroll
                for (int in_ = 0; in_ < 4; in_++) {
                    mma_tf32(d[im][in_], ahi[im], bhi[in_]);
                    mma_tf32(d[im][in_], ahi[im], blo[in_]);
                    mma_tf32(d[im][in_], alo[im], bhi[in_]);
                }
        }
        __syncthreads();
    }

    // epilogue: c0 (r,c), c1 (r,c+1), c2 (r+8,c), c3 (r+8,c+1)
#pragma unroll
    for (int im = 0; im < 4; im++) {
#pragma unroll
        for (int in_ = 0; in_ < 4; in_++) {
            int row = row0 + wm + im * 16 + (lane >> 2);
            int col = col0 + wn + in_ * 8 + (lane & 3) * 2;
            float2 bv = *(const float2*)&bias[col];
            float2 o0 = make_float2(d[im][in_][0] + bv.x, d[im][in_][1] + bv.y);
            float2 o1 = make_float2(d[im][in_][2] + bv.x, d[im][in_][3] + bv.y);
            *(float2*)&C[(long long)row * N + col]       = o0;
            *(float2*)&C[(long long)(row + 8) * N + col] = o1;
        }
    }
}

__global__ __launch_bounds__(256)
void gemm_tf32_kernel(GemmArgs g0, GemmArgs g1, GemmArgs g2, int M, int N, int K)
{
    GemmArgs g = (blockIdx.z == 0) ? g0 : (blockIdx.z == 1) ? g1 : g2;
    gemm_tf32_body(g.A, g.W, g.bias, g.C, M, N, K);
}

// ---------------------------------------------------------------------------
// Tiled banded attention. Block = 64 queries of one (b,h), 256 threads.
// smem (floats): Qs[64][68] (Qs[d][qi])          off 0      4352
//                KV: Ks[64][132] then Vs[128][68] off 4352   8704 (aliased)
//                Ss[64][132]                      off 13056  8448
//                sinv[64]                         off 21504  64
// total 21568 floats = 86272 bytes -> 2 CTAs/SM
// ---------------------------------------------------------------------------
#define SM_QS 0
#define SM_KV 4352
#define SM_SS 13056
#define SM_INV 21504
#define ATTN_SMEM_BYTES (21568 * 4)

__global__ __launch_bounds__(256)
void attn_tile_kernel(const float* __restrict__ Qp, const float* __restrict__ Kp,
                      const float* __restrict__ Vp, float* __restrict__ concatOut,
                      int rowOffset, float* __restrict__ Aout)
{
    extern __shared__ float sm[];
    float* Qs = sm + SM_QS;
    float* KV = sm + SM_KV;     // Ks[d][kj] stride 132, later Vs[kj][d] stride 68
    float* Ss = sm + SM_SS;
    float* sinv = sm + SM_INV;

    int tid = threadIdx.x;
    int q0 = blockIdx.x * 64;
    int h  = blockIdx.y;
    int b  = blockIdx.z;
    int k0 = q0 - HALFW;
    const float scale = 0.125f;

    long long headBase = (long long)b * Pc * Dc + (long long)h * DKc;

    // Load Q tile transposed into Qs[d][qi]
    {
        int r = tid >> 2;
        int c = (tid & 3) * 16;
#pragma unroll
        for (int cc = 0; cc < 16; cc += 4) {
            float4 v = *(const float4*)&Qp[headBase + (long long)(q0 + r) * Dc + c + cc];
            Qs[(c + cc + 0) * 68 + r] = v.x;
            Qs[(c + cc + 1) * 68 + r] = v.y;
            Qs[(c + cc + 2) * 68 + r] = v.z;
            Qs[(c + cc + 3) * 68 + r] = v.w;
        }
    }
    // Load K transposed into KV as Ks[d][kj]
    for (int t = tid; t < 128 * 16; t += 256) {
        int r = t >> 4;
        int c = (t & 15) * 4;
        int j = k0 + r;
        float4 kv = make_float4(0.f, 0.f, 0.f, 0.f);
        if (j >= 0 && j < Pc)
            kv = *(const float4*)&Kp[headBase + (long long)j * Dc + c];
        KV[(c + 0) * 132 + r] = kv.x;
        KV[(c + 1) * 132 + r] = kv.y;
        KV[(c + 2) * 132 + r] = kv.z;
        KV[(c + 3) * 132 + r] = kv.w;
    }
    __syncthreads();

    // GEMM1: S[64][128] = Q * K^T ; thread -> 4(qi) x 8(kj)
    {
        int tx = tid & 15;
        int ty = tid >> 4;
        float acc[4][8];
#pragma unroll
        for (int i = 0; i < 4; i++)
#pragma unroll
            for (int j = 0; j < 8; j++) acc[i][j] = 0.f;

#pragma unroll 4
        for (int dd = 0; dd < 64; dd++) {
            float4 a  = *(const float4*)&Qs[dd * 68 + ty * 4];
            float4 b0 = *(const float4*)&KV[dd * 132 + tx * 8];
            float4 b1 = *(const float4*)&KV[dd * 132 + tx * 8 + 4];
            float ar[4] = {a.x, a.y, a.z, a.w};
            float br[8] = {b0.x, b0.y, b0.z, b0.w, b1.x, b1.y, b1.z, b1.w};
#pragma unroll
            for (int i = 0; i < 4; i++)
#pragma unroll
                for (int j = 0; j < 8; j++)
                    acc[i][j] = fmaf(ar[i], br[j], acc[i][j]);
        }
#pragma unroll
        for (int i = 0; i < 4; i++) {
            int row = ty * 4 + i;
            *(float4*)&Ss[row * 132 + tx * 8] =
                make_float4(acc[i][0], acc[i][1], acc[i][2], acc[i][3]);
            *(float4*)&Ss[row * 132 + tx * 8 + 4] =
                make_float4(acc[i][4], acc[i][5], acc[i][6], acc[i][7]);
        }
    }
    __syncthreads();

    // Load V over dead K region: Vs[kj][d] stride 68
    for (int t = tid; t < 128 * 16; t += 256) {
        int r = t >> 4;
        int c = (t & 15) * 4;
        int j = k0 + r;
        float4 vv = make_float4(0.f, 0.f, 0.f, 0.f);
        if (j >= 0 && j < Pc)
            vv = *(const float4*)&Vp[headBase + (long long)j * Dc + c];
        *(float4*)&KV[r * 68 + c] = vv;
    }

    // Parallel softmax: 4 threads per row, interleaved columns (bank-free)
    int qi = tid >> 2;
    int p  = tid & 3;
    int i_glob = q0 + qi;
    int jlo = i_glob - HALFW; if (jlo < 0) jlo = 0;
    int jhi = i_glob + HALFW; if (jhi > Pc - 1) jhi = Pc - 1;
    int kjlo = jlo - k0;
    int kjhi = jhi - k0;
    {
        float* srow = &Ss[qi * 132];
        float m = -1e30f;
#pragma unroll 8
        for (int t = 0; t < 32; t++) {
            int kj = p + 4 * t;
            if (kj >= kjlo && kj <= kjhi) m = fmaxf(m, srow[kj]);
        }
        m = fmaxf(m, __shfl_xor_sync(0xffffffffu, m, 1));
        m = fmaxf(m, __shfl_xor_sync(0xffffffffu, m, 2));
        float sum = 0.f;
#pragma unroll 8
        for (int t = 0; t < 32; t++) {
            int kj = p + 4 * t;
            float pv = 0.f;
            if (kj >= kjlo && kj <= kjhi) {
                pv = __expf(scale * (srow[kj] - m));
                sum += pv;
            }
            srow[kj] = pv;
        }
        sum += __shfl_xor_sync(0xffffffffu, sum, 1);
        sum += __shfl_xor_sync(0xffffffffu, sum, 2);
        if (p == 0) sinv[qi] = 1.0f / sum;
    }
    __syncthreads();

    // GEMM2: O[64][64] = P * V ; thread -> 4(qi) x 4(d)
    {
        int txd = tid & 15;
        int tyq = tid >> 4;
        float acc[4][4];
#pragma unroll
        for (int i = 0; i < 4; i++)
#pragma unroll
            for (int j = 0; j < 4; j++) acc[i][j] = 0.f;

#pragma unroll 4
        for (int kj = 0; kj < 128; kj++) {
            float4 bv = *(const float4*)&KV[kj * 68 + txd * 4];
            float br[4] = {bv.x, bv.y, bv.z, bv.w};
#pragma unroll
            for (int i = 0; i < 4; i++) {
                float a = Ss[(tyq * 4 + i) * 132 + kj];
#pragma unroll
                for (int j = 0; j < 4; j++)
                    acc[i][j] = fmaf(a, br[j], acc[i][j]);
            }
        }
#pragma unroll
        for (int i = 0; i < 4; i++) {
            int qq = tyq * 4 + i;
            float inv = sinv[qq];
            long long dst = ((long long)b * CONCAT_P + rowOffset + q0 + qq) * Dc
                            + h * DKc + txd * 4;
            *(float4*)&concatOut[dst] = make_float4(acc[i][0] * inv, acc[i][1] * inv,
                                                    acc[i][2] * inv, acc[i][3] * inv);
        }
    }

    // Dense A row write (zeros outside band) — DRAM pipe is idle here
    if (Aout) {
        float inv = sinv[qi];
        long long arow = (((long long)b * Hc + h) * Pc + i_glob) * (long long)Pc;
        float* srow = &Ss[qi * 132];
#pragma unroll 4
        for (int t = 0; t < 64; t++) {
            int j0 = p * 256 + t * 4;
            float4 v = make_float4(0.f, 0.f, 0.f, 0.f);
            if (j0 + 3 >= jlo && j0 <= jhi) {
                int j;
                j = j0 + 0; if (j >= jlo && j <= jhi) v.x = srow[j - k0] * inv;
                j = j0 + 1; if (j >= jlo && j <= jhi) v.y = srow[j - k0] * inv;
                j = j0 + 2; if (j >= jlo && j <= jhi) v.z = srow[j - k0] * inv;
                j = j0 + 3; if (j >= jlo && j <= jhi) v.w = srow[j - k0] * inv;
            }
            *(float4*)&Aout[arow + j0] = v;
        }
    }
}

// ---------------------------------------------------------------------------
extern "C" void kernel_launch(void* const* d_in, const int* in_sizes, int n_in,
                              void* d_out, int out_size)
{
    const float* queries = (const float*)d_in[0];
    const float* keys    = (const float*)d_in[1];
    const float* values  = (const float*)d_in[2];
    const float* Wq = (const float*)d_in[3];
    const float* bq = (const float*)d_in[4];
    const float* Wk = (const float*)d_in[5];
    const float* bk = (const float*)d_in[6];
    const float* Wv = (const float*)d_in[7];
    const float* bv = (const float*)d_in[8];
    const float* Wo = (const float*)d_in[9];
    const float* bo = (const float*)d_in[10];

    float* out = (float*)d_out;

    float *Qb, *Kb, *Vb, *Cb;
    cudaGetSymbolAddress((void**)&Qb, g_Q);
    cudaGetSymbolAddress((void**)&Kb, g_K);
    cudaGetSymbolAddress((void**)&Vb, g_V);
    cudaGetSymbolAddress((void**)&Cb, g_concat);

    static int attr_set = 0;
    if (!attr_set) {
        cudaFuncSetAttribute(attn_tile_kernel,
                             cudaFuncAttributeMaxDynamicSharedMemorySize,
                             ATTN_SMEM_BYTES);
        attr_set = 1;
    }

    const int M1 = Bc * Pc;        // 4096
    const int M2 = Bc * CONCAT_P;  // 8192
    const int N = Dc, K = Dc;

    const long long mainN = (long long)Bc * CONCAT_P * Dc;   // 4,194,304
    const long long aN    = (long long)Bc * Hc * Pc * Pc;    // 33,554,432
    float* A1 = nullptr;
    float* A2 = nullptr;
    if ((long long)out_size >= mainN + 2 * aN) {
        A1 = out + mainN;
        A2 = A1 + aN;
    }

    GemmArgs gq = {queries, Wq, bq, Qb};
    GemmArgs gk = {keys,    Wk, bk, Kb};
    GemmArgs gv = {values,  Wv, bv, Vb};
    dim3 g1(N / 128, M1 / 128, 3);
    gemm_tf32_kernel<<<g1, 256>>>(gq, gk, gv, M1, N, K);

    dim3 ga(Pc / 64, Hc, Bc);
    attn_tile_kernel<<<ga, 256, ATTN_SMEM_BYTES>>>(Qb, Kb, Vb, Cb, 0,  A1);
    attn_tile_kernel<<<ga, 256, ATTN_SMEM_BYTES>>>(Kb, Qb, Qb, Cb, Pc, A2);

    GemmArgs go = {Cb, Wo, bo, out};
    dim3 g2(N / 128, M2 / 128, 1);
    gemm_tf32_kernel<<<g2, 256>>>(go, go, go, M2, N, K);
}

// round 4
// speedup vs baseline: 1.3827x; 1.3827x over previous
#include <cuda_runtime.h>
#include <cuda_bf16.h>
#include <math.h>

#define Bc   4
#define Pc   1024
#define Dc   512
#define Hc   8
#define DKc  64
#define HALFW 32
#define CONCAT_P (2*Pc)

#define M_PROJ (Bc * Pc)        // 4096
#define M_OUT  (Bc * CONCAT_P)  // 8192

// fp32 intermediates
__device__ float g_QKV[3 * M_PROJ * Dc];      // Q | K | V projections

// bf16 hi/lo split operands
__device__ __nv_bfloat16 g_Ahi[3 * M_PROJ * Dc];
__device__ __nv_bfloat16 g_Alo[3 * M_PROJ * Dc];
__device__ __nv_bfloat16 g_Bhi[4 * Dc * Dc];   // Wq,Wk,Wv,Wo transposed [n][k]
__device__ __nv_bfloat16 g_Blo[4 * Dc * Dc];
__device__ __nv_bfloat16 g_Chi[M_OUT * Dc];    // concat, written by attention
__device__ __nv_bfloat16 g_Clo[M_OUT * Dc];

// ---------------------------------------------------------------------------
// Split helpers
// ---------------------------------------------------------------------------
__device__ __forceinline__ void split_bf16(float v, __nv_bfloat16& hi, __nv_bfloat16& lo)
{
    hi = __float2bfloat16(v);
    lo = __float2bfloat16(v - __bfloat162float(hi));
}

// Split 3 activation inputs (row-major [M][512]) into hi/lo, layout unchanged.
__global__ void split_a_kernel(const float* __restrict__ s0, const float* __restrict__ s1,
                               const float* __restrict__ s2,
                               __nv_bfloat16* __restrict__ hi, __nv_bfloat16* __restrict__ lo)
{
    int z = blockIdx.z;
    const float* src = (z == 0) ? s0 : (z == 1) ? s1 : s2;
    long long base = (long long)z * M_PROJ * Dc;
    long long n4 = (long long)M_PROJ * Dc / 4;
    long long idx = (long long)blockIdx.x * blockDim.x + threadIdx.x;
    long long stride = (long long)gridDim.x * blockDim.x;
    for (long long i = idx; i < n4; i += stride) {
        float4 v = ((const float4*)src)[i];
        __nv_bfloat16 h[4], l[4];
        split_bf16(v.x, h[0], l[0]);
        split_bf16(v.y, h[1], l[1]);
        split_bf16(v.z, h[2], l[2]);
        split_bf16(v.w, h[3], l[3]);
        long long o = base + i * 4;
        *(__nv_bfloat162*)&hi[o]     = __nv_bfloat162(h[0], h[1]);
        *(__nv_bfloat162*)&hi[o + 2] = __nv_bfloat162(h[2], h[3]);
        *(__nv_bfloat162*)&lo[o]     = __nv_bfloat162(l[0], l[1]);
        *(__nv_bfloat162*)&lo[o + 2] = __nv_bfloat162(l[2], l[3]);
    }
}

// Transpose + split weights: W[k][n] (512x512) -> out[n][k] hi/lo
__global__ void split_b_kernel(const float* __restrict__ w0, const float* __restrict__ w1,
                               const float* __restrict__ w2, const float* __restrict__ w3,
                               __nv_bfloat16* __restrict__ hi, __nv_bfloat16* __restrict__ lo)
{
    __shared__ float t[32][33];
    int z = blockIdx.z;
    const float* W = (z == 0) ? w0 : (z == 1) ? w1 : (z == 2) ? w2 : w3;
    long long base = (long long)z * Dc * Dc;
    int n0 = blockIdx.x * 32;
    int k0 = blockIdx.y * 32;
    int tx = threadIdx.x, ty = threadIdx.y;   // 32 x 8
#pragma unroll
    for (int i = 0; i < 4; i++)
        t[ty + i * 8][tx] = W[(long long)(k0 + ty + i * 8) * Dc + n0 + tx];
    __syncthreads();
#pragma unroll
    for (int i = 0; i < 4; i++) {
        float v = t[tx][ty + i * 8];
        long long o = base + (long long)(n0 + ty + i * 8) * Dc + k0 + tx;
        __nv_bfloat16 h, l;
        split_bf16(v, h, l);
        hi[o] = h;
        lo[o] = l;
    }
}

// ---------------------------------------------------------------------------
// bf16-split GEMM: C[M,512] = A[M,512] @ B^T (B stored [n][k]) + bias
// C = Ahi*Bhi + Ahi*Blo + Alo*Bhi  (fp32 accum). Block 128x128, BK=32,
// 256 threads (8 warps 2m x 4n, warp tile 64x32), cp.async 2-stage.
// ---------------------------------------------------------------------------
#define GS_STRIDE 40                 // smem row stride in bf16 (conflict-free)
#define GS_TILE   (128 * GS_STRIDE)  // 5120 bf16 per array
#define GS_STAGE  (4 * GS_TILE)      // Ah,Al,Bh,Bl
#define GEMM_SMEM_BYTES (2 * GS_STAGE * 2)   // 81920

__device__ __forceinline__ void cpasync16(void* dst_sh, const void* src)
{
    unsigned sh = (unsigned)__cvta_generic_to_shared(dst_sh);
    asm volatile("cp.async.cg.shared.global [%0], [%1], 16;\n" :: "r"(sh), "l"(src));
}

__device__ __forceinline__ void mma_bf16(float* d, const unsigned* a, const unsigned* b)
{
    asm volatile(
        "mma.sync.aligned.m16n8k16.row.col.f32.bf16.bf16.f32 "
        "{%0,%1,%2,%3}, {%4,%5,%6,%7}, {%8,%9}, {%0,%1,%2,%3};"
        : "+f"(d[0]), "+f"(d[1]), "+f"(d[2]), "+f"(d[3])
        : "r"(a[0]), "r"(a[1]), "r"(a[2]), "r"(a[3]), "r"(b[0]), "r"(b[1]));
}

__global__ __launch_bounds__(256)
void gemm_split_kernel(const __nv_bfloat16* __restrict__ Ah, const __nv_bfloat16* __restrict__ Al,
                       long long aStrideZ,
                       const __nv_bfloat16* __restrict__ Bh, const __nv_bfloat16* __restrict__ Bl,
                       long long bStrideZ,
                       float* __restrict__ C, long long cStrideZ,
                       const float* b0, const float* b1, const float* b2,
                       int M)
{
    extern __shared__ __nv_bfloat16 smem[];
    int z = blockIdx.z;
    Ah += (long long)z * aStrideZ;
    Al += (long long)z * aStrideZ;
    Bh += (long long)z * bStrideZ;
    Bl += (long long)z * bStrideZ;
    C  += (long long)z * cStrideZ;
    const float* bias = (z == 0) ? b0 : (z == 1) ? b1 : b2;

    int tid  = threadIdx.x;
    int lane = tid & 31;
    int warp = tid >> 5;
    int wm = (warp & 1) * 64;
    int wn = (warp >> 1) * 32;
    int row0 = blockIdx.y * 128;
    int col0 = blockIdx.x * 128;

    // per-thread copy map: 8 chunks of 16B
    int cp_arr[8], cp_row[8], cp_c[8];
#pragma unroll
    for (int i = 0; i < 8; i++) {
        cp_arr[i] = i >> 1;
        int idx2 = ((i & 1) << 8) + tid;
        cp_row[i] = idx2 >> 2;
        cp_c[i] = (idx2 & 3) * 8;    // bf16 offset of 16B chunk
    }

    float acc[4][4][4];
#pragma unroll
    for (int im = 0; im < 4; im++)
#pragma unroll
        for (int in_ = 0; in_ < 4; in_++)
#pragma unroll
            for (int r = 0; r < 4; r++) acc[im][in_][r] = 0.f;

    const int nIt = Dc / 32;

    // stage load
    auto load_stage = [&](int it, int s) {
        __nv_bfloat16* st = smem + s * GS_STAGE;
        int k0 = it * 32;
#pragma unroll
        for (int i = 0; i < 8; i++) {
            const __nv_bfloat16* src;
            int row = cp_row[i];
            int c = cp_c[i];
            if (cp_arr[i] == 0)      src = Ah + (long long)(row0 + row) * Dc + k0 + c;
            else if (cp_arr[i] == 1) src = Al + (long long)(row0 + row) * Dc + k0 + c;
            else if (cp_arr[i] == 2) src = Bh + (long long)(col0 + row) * Dc + k0 + c;
            else                     src = Bl + (long long)(col0 + row) * Dc + k0 + c;
            cpasync16(st + cp_arr[i] * GS_TILE + row * GS_STRIDE + c, src);
        }
        asm volatile("cp.async.commit_group;\n" ::);
    };

    load_stage(0, 0);

    for (int it = 0; it < nIt; it++) {
        int buf = it & 1;
        if (it + 1 < nIt) {
            load_stage(it + 1, buf ^ 1);
            asm volatile("cp.async.wait_group 1;\n" ::);
        } else {
            asm volatile("cp.async.wait_group 0;\n" ::);
        }
        __syncthreads();

        const __nv_bfloat16* sAh = smem + buf * GS_STAGE;
        const __nv_bfloat16* sAl = sAh + GS_TILE;
        const __nv_bfloat16* sBh = sAl + GS_TILE;
        const __nv_bfloat16* sBl = sBh + GS_TILE;

#pragma unroll
        for (int kk = 0; kk < 32; kk += 16) {
            int acol = kk + 2 * (lane & 3);
            unsigned a_h[4][4], a_l[4][4];
#pragma unroll
            for (int im = 0; im < 4; im++) {
                int rbase = wm + im * 16 + (lane >> 2);
#pragma unroll
                for (int r = 0; r < 4; r++) {
                    int row = rbase + (r & 1) * 8;
                    int col = acol + (r >> 1) * 8;
                    a_h[im][r] = *(const unsigned*)&sAh[row * GS_STRIDE + col];
                    a_l[im][r] = *(const unsigned*)&sAl[row * GS_STRIDE + col];
                }
            }
            unsigned b_h[4][2], b_l[4][2];
#pragma unroll
            for (int in_ = 0; in_ < 4; in_++) {
                int nrow = wn + in_ * 8 + (lane >> 2);
#pragma unroll
                for (int r = 0; r < 2; r++) {
                    int col = acol + r * 8;
                    b_h[in_][r] = *(const unsigned*)&sBh[nrow * GS_STRIDE + col];
                    b_l[in_][r] = *(const unsigned*)&sBl[nrow * GS_STRIDE + col];
                }
            }
#pragma unroll
            for (int im = 0; im < 4; im++)
#pragma unroll
                for (int in_ = 0; in_ < 4; in_++) {
                    mma_bf16(acc[im][in_], a_h[im], b_h[in_]);
                    mma_bf16(acc[im][in_], a_h[im], b_l[in_]);
                    mma_bf16(acc[im][in_], a_l[im], b_h[in_]);
                }
        }
        __syncthreads();
    }

    // epilogue
#pragma unroll
    for (int im = 0; im < 4; im++) {
#pragma unroll
        for (int in_ = 0; in_ < 4; in_++) {
            int row = row0 + wm + im * 16 + (lane >> 2);
            int col = col0 + wn + in_ * 8 + 2 * (lane & 3);
            float2 bv = *(const float2*)&bias[col];
            float2 o0 = make_float2(acc[im][in_][0] + bv.x, acc[im][in_][1] + bv.y);
            float2 o1 = make_float2(acc[im][in_][2] + bv.x, acc[im][in_][3] + bv.y);
            *(float2*)&C[(long long)row * Dc + col]       = o0;
            *(float2*)&C[(long long)(row + 8) * Dc + col] = o1;
        }
    }
}

// ---------------------------------------------------------------------------
// Banded attention tile kernel (as round 3, epilogue now writes bf16 hi/lo)
// ---------------------------------------------------------------------------
#define SM_QS 0
#define SM_KV 4352
#define SM_SS 13056
#define SM_INV 21504
#define ATTN_SMEM_BYTES (21568 * 4)

__global__ __launch_bounds__(256)
void attn_tile_kernel(const float* __restrict__ Qp, const float* __restrict__ Kp,
                      const float* __restrict__ Vp,
                      __nv_bfloat16* __restrict__ Chi, __nv_bfloat16* __restrict__ Clo,
                      int rowOffset, float* __restrict__ Aout)
{
    extern __shared__ float sm[];
    float* Qs = sm + SM_QS;
    float* KV = sm + SM_KV;
    float* Ss = sm + SM_SS;
    float* sinv = sm + SM_INV;

    int tid = threadIdx.x;
    int q0 = blockIdx.x * 64;
    int h  = blockIdx.y;
    int b  = blockIdx.z;
    int k0 = q0 - HALFW;
    const float scale = 0.125f;

    long long headBase = (long long)b * Pc * Dc + (long long)h * DKc;

    {
        int r = tid >> 2;
        int c = (tid & 3) * 16;
#pragma unroll
        for (int cc = 0; cc < 16; cc += 4) {
            float4 v = *(const float4*)&Qp[headBase + (long long)(q0 + r) * Dc + c + cc];
            Qs[(c + cc + 0) * 68 + r] = v.x;
            Qs[(c + cc + 1) * 68 + r] = v.y;
            Qs[(c + cc + 2) * 68 + r] = v.z;
            Qs[(c + cc + 3) * 68 + r] = v.w;
        }
    }
    for (int t = tid; t < 128 * 16; t += 256) {
        int r = t >> 4;
        int c = (t & 15) * 4;
        int j = k0 + r;
        float4 kv = make_float4(0.f, 0.f, 0.f, 0.f);
        if (j >= 0 && j < Pc)
            kv = *(const float4*)&Kp[headBase + (long long)j * Dc + c];
        KV[(c + 0) * 132 + r] = kv.x;
        KV[(c + 1) * 132 + r] = kv.y;
        KV[(c + 2) * 132 + r] = kv.z;
        KV[(c + 3) * 132 + r] = kv.w;
    }
    __syncthreads();

    {
        int tx = tid & 15;
        int ty = tid >> 4;
        float acc[4][8];
#pragma unroll
        for (int i = 0; i < 4; i++)
#pragma unroll
            for (int j = 0; j < 8; j++) acc[i][j] = 0.f;

#pragma unroll 4
        for (int dd = 0; dd < 64; dd++) {
            float4 a  = *(const float4*)&Qs[dd * 68 + ty * 4];
            float4 b0 = *(const float4*)&KV[dd * 132 + tx * 8];
            float4 b1 = *(const float4*)&KV[dd * 132 + tx * 8 + 4];
            float ar[4] = {a.x, a.y, a.z, a.w};
            float br[8] = {b0.x, b0.y, b0.z, b0.w, b1.x, b1.y, b1.z, b1.w};
#pragma unroll
            for (int i = 0; i < 4; i++)
#pragma unroll
                for (int j = 0; j < 8; j++)
                    acc[i][j] = fmaf(ar[i], br[j], acc[i][j]);
        }
#pragma unroll
        for (int i = 0; i < 4; i++) {
            int row = ty * 4 + i;
            *(float4*)&Ss[row * 132 + tx * 8] =
                make_float4(acc[i][0], acc[i][1], acc[i][2], acc[i][3]);
            *(float4*)&Ss[row * 132 + tx * 8 + 4] =
                make_float4(acc[i][4], acc[i][5], acc[i][6], acc[i][7]);
        }
    }
    __syncthreads();

    for (int t = tid; t < 128 * 16; t += 256) {
        int r = t >> 4;
        int c = (t & 15) * 4;
        int j = k0 + r;
        float4 vv = make_float4(0.f, 0.f, 0.f, 0.f);
        if (j >= 0 && j < Pc)
            vv = *(const float4*)&Vp[headBase + (long long)j * Dc + c];
        *(float4*)&KV[r * 68 + c] = vv;
    }

    int qi = tid >> 2;
    int p  = tid & 3;
    int i_glob = q0 + qi;
    int jlo = i_glob - HALFW; if (jlo < 0) jlo = 0;
    int jhi = i_glob + HALFW; if (jhi > Pc - 1) jhi = Pc - 1;
    int kjlo = jlo - k0;
    int kjhi = jhi - k0;
    {
        float* srow = &Ss[qi * 132];
        float m = -1e30f;
#pragma unroll 8
        for (int t = 0; t < 32; t++) {
            int kj = p + 4 * t;
            if (kj >= kjlo && kj <= kjhi) m = fmaxf(m, srow[kj]);
        }
        m = fmaxf(m, __shfl_xor_sync(0xffffffffu, m, 1));
        m = fmaxf(m, __shfl_xor_sync(0xffffffffu, m, 2));
        float sum = 0.f;
#pragma unroll 8
        for (int t = 0; t < 32; t++) {
            int kj = p + 4 * t;
            float pv = 0.f;
            if (kj >= kjlo && kj <= kjhi) {
                pv = __expf(scale * (srow[kj] - m));
                sum += pv;
            }
            srow[kj] = pv;
        }
        sum += __shfl_xor_sync(0xffffffffu, sum, 1);
        sum += __shfl_xor_sync(0xffffffffu, sum, 2);
        if (p == 0) sinv[qi] = 1.0f / sum;
    }
    __syncthreads();

    {
        int txd = tid & 15;
        int tyq = tid >> 4;
        float acc[4][4];
#pragma unroll
        for (int i = 0; i < 4; i++)
#pragma unroll
            for (int j = 0; j < 4; j++) acc[i][j] = 0.f;

#pragma unroll 4
        for (int kj = 0; kj < 128; kj++) {
            float4 bv = *(const float4*)&KV[kj * 68 + txd * 4];
            float br[4] = {bv.x, bv.y, bv.z, bv.w};
#pragma unroll
            for (int i = 0; i < 4; i++) {
                float a = Ss[(tyq * 4 + i) * 132 + kj];
#pragma unroll
                for (int j = 0; j < 4; j++)
                    acc[i][j] = fmaf(a, br[j], acc[i][j]);
            }
        }
#pragma unroll
        for (int i = 0; i < 4; i++) {
            int qq = tyq * 4 + i;
            float inv = sinv[qq];
            long long dst = ((long long)b * CONCAT_P + rowOffset + q0 + qq) * Dc
                            + h * DKc + txd * 4;
            float o[4] = {acc[i][0] * inv, acc[i][1] * inv, acc[i][2] * inv, acc[i][3] * inv};
            __nv_bfloat16 hh[4], ll[4];
#pragma unroll
            for (int j = 0; j < 4; j++) split_bf16(o[j], hh[j], ll[j]);
            *(__nv_bfloat162*)&Chi[dst]     = __nv_bfloat162(hh[0], hh[1]);
            *(__nv_bfloat162*)&Chi[dst + 2] = __nv_bfloat162(hh[2], hh[3]);
            *(__nv_bfloat162*)&Clo[dst]     = __nv_bfloat162(ll[0], ll[1]);
            *(__nv_bfloat162*)&Clo[dst + 2] = __nv_bfloat162(ll[2], ll[3]);
        }
    }

    if (Aout) {
        float inv = sinv[qi];
        long long arow = (((long long)b * Hc + h) * Pc + i_glob) * (long long)Pc;
        float* srow = &Ss[qi * 132];
#pragma unroll 4
        for (int t = 0; t < 64; t++) {
            int j0 = p * 256 + t * 4;
            float4 v = make_float4(0.f, 0.f, 0.f, 0.f);
            if (j0 + 3 >= jlo && j0 <= jhi) {
                int j;
                j = j0 + 0; if (j >= jlo && j <= jhi) v.x = srow[j - k0] * inv;
                j = j0 + 1; if (j >= jlo && j <= jhi) v.y = srow[j - k0] * inv;
                j = j0 + 2; if (j >= jlo && j <= jhi) v.z = srow[j - k0] * inv;
                j = j0 + 3; if (j >= jlo && j <= jhi) v.w = srow[j - k0] * inv;
            }
            *(float4*)&Aout[arow + j0] = v;
        }
    }
}

// ---------------------------------------------------------------------------
extern "C" void kernel_launch(void* const* d_in, const int* in_sizes, int n_in,
                              void* d_out, int out_size)
{
    const float* queries = (const float*)d_in[0];
    const float* keys    = (const float*)d_in[1];
    const float* values  = (const float*)d_in[2];
    const float* Wq = (const float*)d_in[3];
    const float* bq = (const float*)d_in[4];
    const float* Wk = (const float*)d_in[5];
    const float* bk = (const float*)d_in[6];
    const float* Wv = (const float*)d_in[7];
    const float* bv = (const float*)d_in[8];
    const float* Wo = (const float*)d_in[9];
    const float* bo = (const float*)d_in[10];

    float* out = (float*)d_out;

    float* QKV;
    __nv_bfloat16 *Ahi, *Alo, *Bhi, *Blo, *Chi, *Clo;
    cudaGetSymbolAddress((void**)&QKV, g_QKV);
    cudaGetSymbolAddress((void**)&Ahi, g_Ahi);
    cudaGetSymbolAddress((void**)&Alo, g_Alo);
    cudaGetSymbolAddress((void**)&Bhi, g_Bhi);
    cudaGetSymbolAddress((void**)&Blo, g_Blo);
    cudaGetSymbolAddress((void**)&Chi, g_Chi);
    cudaGetSymbolAddress((void**)&Clo, g_Clo);

    static int attr_set = 0;
    if (!attr_set) {
        cudaFuncSetAttribute(attn_tile_kernel,
                             cudaFuncAttributeMaxDynamicSharedMemorySize, ATTN_SMEM_BYTES);
        cudaFuncSetAttribute(gemm_split_kernel,
                             cudaFuncAttributeMaxDynamicSharedMemorySize, GEMM_SMEM_BYTES);
        attr_set = 1;
    }

    const long long mainN = (long long)M_OUT * Dc;           // 4,194,304
    const long long aN    = (long long)Bc * Hc * Pc * Pc;    // 33,554,432
    float* A1 = nullptr;
    float* A2 = nullptr;
    if ((long long)out_size >= mainN + 2 * aN) {
        A1 = out + mainN;
        A2 = A1 + aN;
    }

    // 1. split inputs + weights
    split_a_kernel<<<dim3(256, 1, 3), 256>>>(queries, keys, values, Ahi, Alo);
    split_b_kernel<<<dim3(16, 16, 4), dim3(32, 8)>>>(Wq, Wk, Wv, Wo, Bhi, Blo);

    // 2. projection GEMMs (z = q,k,v)
    const long long aStride = (long long)M_PROJ * Dc;
    const long long bStride = (long long)Dc * Dc;
    gemm_split_kernel<<<dim3(Dc / 128, M_PROJ / 128, 3), 256, GEMM_SMEM_BYTES>>>(
        Ahi, Alo, aStride, Bhi, Blo, bStride, QKV, aStride, bq, bk, bv, M_PROJ);

    // 3. attention
    const float* Qp = QKV;
    const float* Kp = QKV + aStride;
    const float* Vp = QKV + 2 * aStride;
    dim3 ga(Pc / 64, Hc, Bc);
    attn_tile_kernel<<<ga, 256, ATTN_SMEM_BYTES>>>(Qp, Kp, Vp, Chi, Clo, 0,  A1);
    attn_tile_kernel<<<ga, 256, ATTN_SMEM_BYTES>>>(Kp, Qp, Qp, Chi, Clo, Pc, A2);

    // 4. output GEMM (B = Wo split, z offset 3)
    gemm_split_kernel<<<dim3(Dc / 128, M_OUT / 128, 1), 256, GEMM_SMEM_BYTES>>>(
        Chi, Clo, 0, Bhi + 3 * bStride, Blo + 3 * bStride, 0, out, 0, bo, bo, bo, M_OUT);
}

// round 5
// speedup vs baseline: 1.9077x; 1.3797x over previous
#include <cuda_runtime.h>
#include <cuda_bf16.h>
#include <math.h>

#define Bc   4
#define Pc   1024
#define Dc   512
#define Hc   8
#define DKc  64
#define HALFW 32
#define CONCAT_P (2*Pc)

#define M_PROJ (Bc * Pc)        // 4096
#define M_OUT  (Bc * CONCAT_P)  // 8192

// fp32 intermediates
__device__ float g_QKV[3 * M_PROJ * Dc];      // Q | K | V projections

// bf16 hi/lo split operands
__device__ __nv_bfloat16 g_Ahi[3 * M_PROJ * Dc];
__device__ __nv_bfloat16 g_Alo[3 * M_PROJ * Dc];
__device__ __nv_bfloat16 g_Bhi[4 * Dc * Dc];   // Wq,Wk,Wv,Wo transposed [n][k]
__device__ __nv_bfloat16 g_Blo[4 * Dc * Dc];
__device__ __nv_bfloat16 g_Chi[M_OUT * Dc];    // concat, written by attention
__device__ __nv_bfloat16 g_Clo[M_OUT * Dc];

// ---------------------------------------------------------------------------
__device__ __forceinline__ void split_bf16(float v, __nv_bfloat16& hi, __nv_bfloat16& lo)
{
    hi = __float2bfloat16(v);
    lo = __float2bfloat16(v - __bfloat162float(hi));
}

__global__ void split_a_kernel(const float* __restrict__ s0, const float* __restrict__ s1,
                               const float* __restrict__ s2,
                               __nv_bfloat16* __restrict__ hi, __nv_bfloat16* __restrict__ lo)
{
    int z = blockIdx.z;
    const float* src = (z == 0) ? s0 : (z == 1) ? s1 : s2;
    long long base = (long long)z * M_PROJ * Dc;
    long long n4 = (long long)M_PROJ * Dc / 4;
    long long idx = (long long)blockIdx.x * blockDim.x + threadIdx.x;
    long long stride = (long long)gridDim.x * blockDim.x;
    for (long long i = idx; i < n4; i += stride) {
        float4 v = ((const float4*)src)[i];
        __nv_bfloat16 h[4], l[4];
        split_bf16(v.x, h[0], l[0]);
        split_bf16(v.y, h[1], l[1]);
        split_bf16(v.z, h[2], l[2]);
        split_bf16(v.w, h[3], l[3]);
        long long o = base + i * 4;
        *(__nv_bfloat162*)&hi[o]     = __nv_bfloat162(h[0], h[1]);
        *(__nv_bfloat162*)&hi[o + 2] = __nv_bfloat162(h[2], h[3]);
        *(__nv_bfloat162*)&lo[o]     = __nv_bfloat162(l[0], l[1]);
        *(__nv_bfloat162*)&lo[o + 2] = __nv_bfloat162(l[2], l[3]);
    }
}

__global__ void split_b_kernel(const float* __restrict__ w0, const float* __restrict__ w1,
                               const float* __restrict__ w2, const float* __restrict__ w3,
                               __nv_bfloat16* __restrict__ hi, __nv_bfloat16* __restrict__ lo)
{
    __shared__ float t[32][33];
    int z = blockIdx.z;
    const float* W = (z == 0) ? w0 : (z == 1) ? w1 : (z == 2) ? w2 : w3;
    long long base = (long long)z * Dc * Dc;
    int n0 = blockIdx.x * 32;
    int k0 = blockIdx.y * 32;
    int tx = threadIdx.x, ty = threadIdx.y;   // 32 x 8
#pragma unroll
    for (int i = 0; i < 4; i++)
        t[ty + i * 8][tx] = W[(long long)(k0 + ty + i * 8) * Dc + n0 + tx];
    __syncthreads();
#pragma unroll
    for (int i = 0; i < 4; i++) {
        float v = t[tx][ty + i * 8];
        long long o = base + (long long)(n0 + ty + i * 8) * Dc + k0 + tx;
        __nv_bfloat16 h, l;
        split_bf16(v, h, l);
        hi[o] = h;
        lo[o] = l;
    }
}

// ---------------------------------------------------------------------------
// bf16-split GEMM (unchanged from round 4)
// ---------------------------------------------------------------------------
#define GS_STRIDE 40
#define GS_TILE   (128 * GS_STRIDE)
#define GS_STAGE  (4 * GS_TILE)
#define GEMM_SMEM_BYTES (2 * GS_STAGE * 2)   // 81920

__device__ __forceinline__ void cpasync16(void* dst_sh, const void* src)
{
    unsigned sh = (unsigned)__cvta_generic_to_shared(dst_sh);
    asm volatile("cp.async.cg.shared.global [%0], [%1], 16;\n" :: "r"(sh), "l"(src));
}

__device__ __forceinline__ void mma_bf16(float* d, const unsigned* a, const unsigned* b)
{
    asm volatile(
        "mma.sync.aligned.m16n8k16.row.col.f32.bf16.bf16.f32 "
        "{%0,%1,%2,%3}, {%4,%5,%6,%7}, {%8,%9}, {%0,%1,%2,%3};"
        : "+f"(d[0]), "+f"(d[1]), "+f"(d[2]), "+f"(d[3])
        : "r"(a[0]), "r"(a[1]), "r"(a[2]), "r"(a[3]), "r"(b[0]), "r"(b[1]));
}

__global__ __launch_bounds__(256)
void gemm_split_kernel(const __nv_bfloat16* __restrict__ Ah, const __nv_bfloat16* __restrict__ Al,
                       long long aStrideZ,
                       const __nv_bfloat16* __restrict__ Bh, const __nv_bfloat16* __restrict__ Bl,
                       long long bStrideZ,
                       float* __restrict__ C, long long cStrideZ,
                       const float* b0, const float* b1, const float* b2,
                       int M)
{
    extern __shared__ __nv_bfloat16 smem[];
    int z = blockIdx.z;
    Ah += (long long)z * aStrideZ;
    Al += (long long)z * aStrideZ;
    Bh += (long long)z * bStrideZ;
    Bl += (long long)z * bStrideZ;
    C  += (long long)z * cStrideZ;
    const float* bias = (z == 0) ? b0 : (z == 1) ? b1 : b2;

    int tid  = threadIdx.x;
    int lane = tid & 31;
    int warp = tid >> 5;
    int wm = (warp & 1) * 64;
    int wn = (warp >> 1) * 32;
    int row0 = blockIdx.y * 128;
    int col0 = blockIdx.x * 128;

    int cp_arr[8], cp_row[8], cp_c[8];
#pragma unroll
    for (int i = 0; i < 8; i++) {
        cp_arr[i] = i >> 1;
        int idx2 = ((i & 1) << 8) + tid;
        cp_row[i] = idx2 >> 2;
        cp_c[i] = (idx2 & 3) * 8;
    }

    float acc[4][4][4];
#pragma unroll
    for (int im = 0; im < 4; im++)
#pragma unroll
        for (int in_ = 0; in_ < 4; in_++)
#pragma unroll
            for (int r = 0; r < 4; r++) acc[im][in_][r] = 0.f;

    const int nIt = Dc / 32;

    auto load_stage = [&](int it, int s) {
        __nv_bfloat16* st = smem + s * GS_STAGE;
        int k0 = it * 32;
#pragma unroll
        for (int i = 0; i < 8; i++) {
            const __nv_bfloat16* src;
            int row = cp_row[i];
            int c = cp_c[i];
            if (cp_arr[i] == 0)      src = Ah + (long long)(row0 + row) * Dc + k0 + c;
            else if (cp_arr[i] == 1) src = Al + (long long)(row0 + row) * Dc + k0 + c;
            else if (cp_arr[i] == 2) src = Bh + (long long)(col0 + row) * Dc + k0 + c;
            else                     src = Bl + (long long)(col0 + row) * Dc + k0 + c;
            cpasync16(st + cp_arr[i] * GS_TILE + row * GS_STRIDE + c, src);
        }
        asm volatile("cp.async.commit_group;\n" ::);
    };

    load_stage(0, 0);

    for (int it = 0; it < nIt; it++) {
        int buf = it & 1;
        if (it + 1 < nIt) {
            load_stage(it + 1, buf ^ 1);
            asm volatile("cp.async.wait_group 1;\n" ::);
        } else {
            asm volatile("cp.async.wait_group 0;\n" ::);
        }
        __syncthreads();

        const __nv_bfloat16* sAh = smem + buf * GS_STAGE;
        const __nv_bfloat16* sAl = sAh + GS_TILE;
        const __nv_bfloat16* sBh = sAl + GS_TILE;
        const __nv_bfloat16* sBl = sBh + GS_TILE;

#pragma unroll
        for (int kk = 0; kk < 32; kk += 16) {
            int acol = kk + 2 * (lane & 3);
            unsigned a_h[4][4], a_l[4][4];
#pragma unroll
            for (int im = 0; im < 4; im++) {
                int rbase = wm + im * 16 + (lane >> 2);
#pragma unroll
                for (int r = 0; r < 4; r++) {
                    int row = rbase + (r & 1) * 8;
                    int col = acol + (r >> 1) * 8;
                    a_h[im][r] = *(const unsigned*)&sAh[row * GS_STRIDE + col];
                    a_l[im][r] = *(const unsigned*)&sAl[row * GS_STRIDE + col];
                }
            }
            unsigned b_h[4][2], b_l[4][2];
#pragma unroll
            for (int in_ = 0; in_ < 4; in_++) {
                int nrow = wn + in_ * 8 + (lane >> 2);
#pragma unroll
                for (int r = 0; r < 2; r++) {
                    int col = acol + r * 8;
                    b_h[in_][r] = *(const unsigned*)&sBh[nrow * GS_STRIDE + col];
                    b_l[in_][r] = *(const unsigned*)&sBl[nrow * GS_STRIDE + col];
                }
            }
#pragma unroll
            for (int im = 0; im < 4; im++)
#pragma unroll
                for (int in_ = 0; in_ < 4; in_++) {
                    mma_bf16(acc[im][in_], a_h[im], b_h[in_]);
                    mma_bf16(acc[im][in_], a_h[im], b_l[in_]);
                    mma_bf16(acc[im][in_], a_l[im], b_h[in_]);
                }
        }
        __syncthreads();
    }

#pragma unroll
    for (int im = 0; im < 4; im++) {
#pragma unroll
        for (int in_ = 0; in_ < 4; in_++) {
            int row = row0 + wm + im * 16 + (lane >> 2);
            int col = col0 + wn + in_ * 8 + 2 * (lane & 3);
            float2 bv = *(const float2*)&bias[col];
            float2 o0 = make_float2(acc[im][in_][0] + bv.x, acc[im][in_][1] + bv.y);
            float2 o1 = make_float2(acc[im][in_][2] + bv.x, acc[im][in_][3] + bv.y);
            *(float2*)&C[(long long)row * Dc + col]       = o0;
            *(float2*)&C[(long long)(row + 8) * Dc + col] = o1;
        }
    }
}

// ---------------------------------------------------------------------------
// Banded attention. grid = (Pc/64, Hc, Bc*2): z = b*2 + which.
// which 0: (Q,K,V) -> concat rows [0,Pc), A1.  which 1: (K,Q,Q) -> [Pc,2Pc), A2.
// Dense A written coalesced: one 4KB row per block iteration, __stcs.
// ---------------------------------------------------------------------------
#define SM_QS 0
#define SM_KV 4352
#define SM_SS 13056
#define SM_INV 21504
#define ATTN_SMEM_BYTES (21568 * 4)

__global__ __launch_bounds__(256)
void attn_tile_kernel(const float* __restrict__ QKV,
                      __nv_bfloat16* __restrict__ Chi, __nv_bfloat16* __restrict__ Clo,
                      float* __restrict__ A1, float* __restrict__ A2)
{
    extern __shared__ float sm[];
    float* Qs = sm + SM_QS;
    float* KV = sm + SM_KV;
    float* Ss = sm + SM_SS;
    float* sinv = sm + SM_INV;

    int tid = threadIdx.x;
    int q0 = blockIdx.x * 64;
    int h  = blockIdx.y;
    int zz = blockIdx.z;
    int b  = zz >> 1;
    int which = zz & 1;
    int k0 = q0 - HALFW;
    const float scale = 0.125f;

    const long long planeStride = (long long)M_PROJ * Dc;
    const float* Qp;
    const float* Kp;
    const float* Vp;
    int rowOffset;
    float* Aout;
    if (which == 0) {
        Qp = QKV;                 Kp = QKV + planeStride; Vp = QKV + 2 * planeStride;
        rowOffset = 0;  Aout = A1;
    } else {
        Qp = QKV + planeStride;   Kp = QKV;               Vp = QKV;
        rowOffset = Pc; Aout = A2;
    }

    long long headBase = (long long)b * Pc * Dc + (long long)h * DKc;

    // Q tile transposed -> Qs[d][qi]
    {
        int r = tid >> 2;
        int c = (tid & 3) * 16;
#pragma unroll
        for (int cc = 0; cc < 16; cc += 4) {
            float4 v = *(const float4*)&Qp[headBase + (long long)(q0 + r) * Dc + c + cc];
            Qs[(c + cc + 0) * 68 + r] = v.x;
            Qs[(c + cc + 1) * 68 + r] = v.y;
            Qs[(c + cc + 2) * 68 + r] = v.z;
            Qs[(c + cc + 3) * 68 + r] = v.w;
        }
    }
    // K transposed -> KV as Ks[d][kj] stride 132
    for (int t = tid; t < 128 * 16; t += 256) {
        int r = t >> 4;
        int c = (t & 15) * 4;
        int j = k0 + r;
        float4 kv = make_float4(0.f, 0.f, 0.f, 0.f);
        if (j >= 0 && j < Pc)
            kv = *(const float4*)&Kp[headBase + (long long)j * Dc + c];
        KV[(c + 0) * 132 + r] = kv.x;
        KV[(c + 1) * 132 + r] = kv.y;
        KV[(c + 2) * 132 + r] = kv.z;
        KV[(c + 3) * 132 + r] = kv.w;
    }
    __syncthreads();

    // GEMM1: S = Q*K^T
    {
        int tx = tid & 15;
        int ty = tid >> 4;
        float acc[4][8];
#pragma unroll
        for (int i = 0; i < 4; i++)
#pragma unroll
            for (int j = 0; j < 8; j++) acc[i][j] = 0.f;

#pragma unroll 4
        for (int dd = 0; dd < 64; dd++) {
            float4 a  = *(const float4*)&Qs[dd * 68 + ty * 4];
            float4 b0 = *(const float4*)&KV[dd * 132 + tx * 8];
            float4 b1 = *(const float4*)&KV[dd * 132 + tx * 8 + 4];
            float ar[4] = {a.x, a.y, a.z, a.w};
            float br[8] = {b0.x, b0.y, b0.z, b0.w, b1.x, b1.y, b1.z, b1.w};
#pragma unroll
            for (int i = 0; i < 4; i++)
#pragma unroll
                for (int j = 0; j < 8; j++)
                    acc[i][j] = fmaf(ar[i], br[j], acc[i][j]);
        }
#pragma unroll
        for (int i = 0; i < 4; i++) {
            int row = ty * 4 + i;
            *(float4*)&Ss[row * 132 + tx * 8] =
                make_float4(acc[i][0], acc[i][1], acc[i][2], acc[i][3]);
            *(float4*)&Ss[row * 132 + tx * 8 + 4] =
                make_float4(acc[i][4], acc[i][5], acc[i][6], acc[i][7]);
        }
    }
    __syncthreads();

    // V over dead K region: Vs[kj][d] stride 68
    for (int t = tid; t < 128 * 16; t += 256) {
        int r = t >> 4;
        int c = (t & 15) * 4;
        int j = k0 + r;
        float4 vv = make_float4(0.f, 0.f, 0.f, 0.f);
        if (j >= 0 && j < Pc)
            vv = *(const float4*)&Vp[headBase + (long long)j * Dc + c];
        *(float4*)&KV[r * 68 + c] = vv;
    }

    // softmax: 4 threads/row
    {
        int qi = tid >> 2;
        int p  = tid & 3;
        int i_glob = q0 + qi;
        int jlo = i_glob - HALFW; if (jlo < 0) jlo = 0;
        int jhi = i_glob + HALFW; if (jhi > Pc - 1) jhi = Pc - 1;
        int kjlo = jlo - k0;
        int kjhi = jhi - k0;
        float* srow = &Ss[qi * 132];
        float m = -1e30f;
#pragma unroll 8
        for (int t = 0; t < 32; t++) {
            int kj = p + 4 * t;
            if (kj >= kjlo && kj <= kjhi) m = fmaxf(m, srow[kj]);
        }
        m = fmaxf(m, __shfl_xor_sync(0xffffffffu, m, 1));
        m = fmaxf(m, __shfl_xor_sync(0xffffffffu, m, 2));
        float sum = 0.f;
#pragma unroll 8
        for (int t = 0; t < 32; t++) {
            int kj = p + 4 * t;
            float pv = 0.f;
            if (kj >= kjlo && kj <= kjhi) {
                pv = __expf(scale * (srow[kj] - m));
                sum += pv;
            }
            srow[kj] = pv;
        }
        sum += __shfl_xor_sync(0xffffffffu, sum, 1);
        sum += __shfl_xor_sync(0xffffffffu, sum, 2);
        if (p == 0) sinv[qi] = 1.0f / sum;
    }
    __syncthreads();

    // GEMM2: O = P*V, epilogue to bf16 hi/lo concat
    {
        int txd = tid & 15;
        int tyq = tid >> 4;
        float acc[4][4];
#pragma unroll
        for (int i = 0; i < 4; i++)
#pragma unroll
            for (int j = 0; j < 4; j++) acc[i][j] = 0.f;

#pragma unroll 4
        for (int kj = 0; kj < 128; kj++) {
            float4 bv = *(const float4*)&KV[kj * 68 + txd * 4];
            float br[4] = {bv.x, bv.y, bv.z, bv.w};
#pragma unroll
            for (int i = 0; i < 4; i++) {
                float a = Ss[(tyq * 4 + i) * 132 + kj];
#pragma unroll
                for (int j = 0; j < 4; j++)
                    acc[i][j] = fmaf(a, br[j], acc[i][j]);
            }
        }
#pragma unroll
        for (int i = 0; i < 4; i++) {
            int qq = tyq * 4 + i;
            float inv = sinv[qq];
            long long dst = ((long long)b * CONCAT_P + rowOffset + q0 + qq) * Dc
                            + h * DKc + txd * 4;
            float o[4] = {acc[i][0] * inv, acc[i][1] * inv, acc[i][2] * inv, acc[i][3] * inv};
            __nv_bfloat16 hh[4], ll[4];
#pragma unroll
            for (int j = 0; j < 4; j++) split_bf16(o[j], hh[j], ll[j]);
            *(__nv_bfloat162*)&Chi[dst]     = __nv_bfloat162(hh[0], hh[1]);
            *(__nv_bfloat162*)&Chi[dst + 2] = __nv_bfloat162(hh[2], hh[3]);
            *(__nv_bfloat162*)&Clo[dst]     = __nv_bfloat162(ll[0], ll[1]);
            *(__nv_bfloat162*)&Clo[dst + 2] = __nv_bfloat162(ll[2], ll[3]);
        }
    }

    // Coalesced dense A write: one row (4KB) per iteration, streaming stores.
    if (Aout) {
        int j0 = tid * 4;                               // this thread's column chunk
        long long abase = ((long long)b * Hc + h) * Pc * (long long)Pc;
#pragma unroll 2
        for (int r = 0; r < 64; r++) {
            int i_glob = q0 + r;
            int jlo = i_glob - HALFW; if (jlo < 0) jlo = 0;
            int jhi = i_glob + HALFW; if (jhi > Pc - 1) jhi = Pc - 1;
            float inv = sinv[r];
            const float* srow = &Ss[r * 132];
            float4 v = make_float4(0.f, 0.f, 0.f, 0.f);
            if (j0 + 3 >= jlo && j0 <= jhi) {
                int j;
                j = j0 + 0; if (j >= jlo && j <= jhi) v.x = srow[j - k0] * inv;
                j = j0 + 1; if (j >= jlo && j <= jhi) v.y = srow[j - k0] * inv;
                j = j0 + 2; if (j >= jlo && j <= jhi) v.z = srow[j - k0] * inv;
                j = j0 + 3; if (j >= jlo && j <= jhi) v.w = srow[j - k0] * inv;
            }
            __stcs((float4*)&Aout[abase + (long long)i_glob * Pc + j0], v);
        }
    }
}

// ---------------------------------------------------------------------------
extern "C" void kernel_launch(void* const* d_in, const int* in_sizes, int n_in,
                              void* d_out, int out_size)
{
    const float* queries = (const float*)d_in[0];
    const float* keys    = (const float*)d_in[1];
    const float* values  = (const float*)d_in[2];
    const float* Wq = (const float*)d_in[3];
    const float* bq = (const float*)d_in[4];
    const float* Wk = (const float*)d_in[5];
    const float* bk = (const float*)d_in[6];
    const float* Wv = (const float*)d_in[7];
    const float* bv = (const float*)d_in[8];
    const float* Wo = (const float*)d_in[9];
    const float* bo = (const float*)d_in[10];

    float* out = (float*)d_out;

    float* QKV;
    __nv_bfloat16 *Ahi, *Alo, *Bhi, *Blo, *Chi, *Clo;
    cudaGetSymbolAddress((void**)&QKV, g_QKV);
    cudaGetSymbolAddress((void**)&Ahi, g_Ahi);
    cudaGetSymbolAddress((void**)&Alo, g_Alo);
    cudaGetSymbolAddress((void**)&Bhi, g_Bhi);
    cudaGetSymbolAddress((void**)&Blo, g_Blo);
    cudaGetSymbolAddress((void**)&Chi, g_Chi);
    cudaGetSymbolAddress((void**)&Clo, g_Clo);

    static int attr_set = 0;
    if (!attr_set) {
        cudaFuncSetAttribute(attn_tile_kernel,
                             cudaFuncAttributeMaxDynamicSharedMemorySize, ATTN_SMEM_BYTES);
        cudaFuncSetAttribute(gemm_split_kernel,
                             cudaFuncAttributeMaxDynamicSharedMemorySize, GEMM_SMEM_BYTES);
        attr_set = 1;
    }

    const long long mainN = (long long)M_OUT * Dc;           // 4,194,304
    const long long aN    = (long long)Bc * Hc * Pc * Pc;    // 33,554,432
    float* A1 = nullptr;
    float* A2 = nullptr;
    if ((long long)out_size >= mainN + 2 * aN) {
        A1 = out + mainN;
        A2 = A1 + aN;
    }

    split_a_kernel<<<dim3(256, 1, 3), 256>>>(queries, keys, values, Ahi, Alo);
    split_b_kernel<<<dim3(16, 16, 4), dim3(32, 8)>>>(Wq, Wk, Wv, Wo, Bhi, Blo);

    const long long aStride = (long long)M_PROJ * Dc;
    const long long bStride = (long long)Dc * Dc;
    gemm_split_kernel<<<dim3(Dc / 128, M_PROJ / 128, 3), 256, GEMM_SMEM_BYTES>>>(
        Ahi, Alo, aStride, Bhi, Blo, bStride, QKV, aStride, bq, bk, bv, M_PROJ);

    dim3 ga(Pc / 64, Hc, Bc * 2);
    attn_tile_kernel<<<ga, 256, ATTN_SMEM_BYTES>>>(QKV, Chi, Clo, A1, A2);

    gemm_split_kernel<<<dim3(Dc / 128, M_OUT / 128, 1), 256, GEMM_SMEM_BYTES>>>(
        Chi, Clo, 0, Bhi + 3 * bStride, Blo + 3 * bStride, 0, out, 0, bo, bo, bo, M_OUT);
}